// round 16
// baseline (speedup 1.0000x reference)
#include <cuda_runtime.h>
#include <cuda_fp16.h>
#include <math_constants.h>
#include <cstdint>

// Max-plus conv2d in fp16x2, two-kernel version.
// K1: convert x fp32 -> fp16 scratch (4MB device global, proven OK in R13/14).
// K2: 128 thr = 16wq x 8hl; thread = 4o x 4w = 8 half2 accs; grid 1024.
//     CCH=8 -> 8 chunks, ONE barrier per chunk. x staged via cp.async
//     double-buffered ring (25.6 KB); k staged per-chunk via LDG fp32 ->
//     convert+duplicate in regs -> STS into a 2.3 KB smem ring (no extra
//     device globals). Compute = 24 (cl,ki) blocks, 1-block reg pipeline.

constexpr int Cc  = 64;
constexpr int Hc  = 64;
constexpr int Wc  = 64;
constexpr int Oc  = 64;
constexpr int Bc  = 8;
constexpr int OT  = 4;
constexpr int HT  = 8;
constexpr int CCH = 8;
constexpr int NCH = Cc / CCH;            // 8 chunks
constexpr int XROWS = HT + 2;            // 10
constexpr int HR    = 80;                // halves per row (160B; col j = w + 8)
constexpr int BUFH  = CCH * XROWS * HR;  // 6400 halves per x ring slot
constexpr int NBUF  = 2;
constexpr int KSLOT = CCH * 9 * OT;      // 288 half2 per k ring slot

__device__ __align__(16) __half g_xh[Bc * Cc * Hc * Wc];   // 4 MB scratch

__global__ __launch_bounds__(256)
void cvt_fp16_kernel(const float* __restrict__ x)
{
    int i = (blockIdx.x * 256 + threadIdx.x) * 4;   // 2M elements total
    float4 v = *(const float4*)(x + i);
    __half2 a = __floats2half2_rn(v.x, v.y);
    __half2 b = __floats2half2_rn(v.z, v.w);
    uint2 u;
    u.x = *reinterpret_cast<uint32_t*>(&a);
    u.y = *reinterpret_cast<uint32_t*>(&b);
    *reinterpret_cast<uint2*>(g_xh + i) = u;
}

__device__ __forceinline__ void cp16(uint32_t s, const void* g) {
    asm volatile("cp.async.cg.shared.global [%0], [%1], 16;\n" :: "r"(s), "l"(g));
}
__device__ __forceinline__ void cp_commit() {
    asm volatile("cp.async.commit_group;\n" ::: "memory");
}
template <int N> __device__ __forceinline__ void cp_wait() {
    asm volatile("cp.async.wait_group %0;\n" :: "n"(N) : "memory");
}
__device__ __forceinline__ __half2 u2h(uint32_t u) {
    return *reinterpret_cast<__half2*>(&u);
}

__global__ __launch_bounds__(128, 7)
void maxplus_fp16_kernel(const float* __restrict__ gk,
                         float* __restrict__ out)
{
    __shared__ __align__(16) __half  sx[NBUF * BUFH];    // 25.6 KB
    __shared__ __align__(16) __half2 skr[NBUF * KSLOT];  // 2.3 KB

    const int bid = blockIdx.x;
    const int ht  = bid & 7;          // 8 h-tiles
    const int ot  = (bid >> 3) & 15;  // 16 o-tiles
    const int b   = bid >> 7;         // 8 batches

    const int h_base = ht * HT;
    const int o_base = ot * OT;

    const int tid = threadIdx.x;      // 0..127
    const int wq  = tid & 15;
    const int hl  = tid >> 4;         // 0..7
    const int wb  = wq * 4;
    const int h   = h_base + hl;

    const __half2 NEG2 = __half2half2(__float2half(-CUDART_INF_F));

    const uint32_t sx_u32 = (uint32_t)__cvta_generic_to_shared(sx);

    // ---- k staging indices: slot idx i -> (oo = i&3, r = i>>2 = cl*9+t) ----
    // gk offset for chunk ch: (o_base+oo)*576 + ch*72 + r.
    const int ki0 = tid;              // always < 288? tid<128 yes
    const int ki1 = tid + 128;        // < 288 always (max 255)
    const int ki2 = tid + 256;        // valid only tid < 32
    const int kof0 = (o_base + (ki0 & 3)) * (Cc * 9) + (ki0 >> 2);
    const int kof1 = (o_base + (ki1 & 3)) * (Cc * 9) + (ki1 >> 2);
    const int kof2 = (tid < KSLOT - 256) ? (o_base + (ki2 & 3)) * (Cc * 9) + (ki2 >> 2) : 0;

    auto k_sts = [&](float a, float c, float e, int bf) {
        __half2* dst = skr + bf * KSLOT;
        dst[ki0] = __half2half2(__float2half_rn(a));
        dst[ki1] = __half2half2(__float2half_rn(c));
        if (tid < KSLOT - 256)
            dst[ki2] = __half2half2(__float2half_rn(e));
    };

    // ---- prefill pads (cp.async never writes them), both x slots ----
    // col j = w + 8; valid w at j=8..71. Reads touch j=6,7 and 72,73.
    for (int rw = tid; rw < NBUF * CCH * XROWS; rw += 128) {
        *reinterpret_cast<__half2*>(sx + rw * HR + 6)  = NEG2;
        *reinterpret_cast<__half2*>(sx + rw * HR + 72) = NEG2;
    }
    // invalid h rows (ht==0 -> local row 0; ht==7 -> local row 9): interiors
    if (ht == 0 || ht == 7) {
        const int r = (ht == 0) ? 0 : (XROWS - 1);
        for (int i = tid; i < NBUF * CCH * 32; i += 128) {   // 32 half2 per row
            int j2 = i & 31;
            int cl = (i >> 5) & (CCH - 1);
            int bf = i / (CCH * 32);
            *reinterpret_cast<__half2*>(
                sx + bf * BUFH + (cl * XROWS + r) * HR + 8 + j2 * 2) = NEG2;
        }
    }

    // ---- x staging geometry: 640 cp16 per chunk = 5 per thread ----
    const __half* xsrc = g_xh + (size_t)b * Cc * Hc * Wc;
    int  gof[5], dof[5];
    bool vr[5];
#pragma unroll
    for (int jj = 0; jj < 5; jj++) {
        int idx = tid + 128 * jj;        // 0..639
        int q   = idx & 7;               // 8 cp16 per row (128B interior)
        int rw  = idx >> 3;              // cl*10 + r, 0..79
        int r   = rw % XROWS;
        int cl  = rw / XROWS;
        int hh  = h_base - 1 + r;
        vr[jj]  = (hh >= 0 && hh < Hc);
        gof[jj] = (cl * Hc + (vr[jj] ? hh : 0)) * Wc + q * 8;
        dof[jj] = (rw * HR + 8 + q * 8) * 2;   // bytes
    }

    auto stage_x = [&](int ch, int bf) {
        const __half* src = xsrc + (size_t)ch * CCH * Hc * Wc;
        const uint32_t dbase = sx_u32 + (uint32_t)(bf * BUFH * 2);
#pragma unroll
        for (int jj = 0; jj < 5; jj++)
            if (vr[jj])
                cp16(dbase + dof[jj], src + gof[jj]);
    };

    // accumulators: acc0[oo]=(wb,wb+1), acc1[oo]=(wb+2,wb+3)
    __half2 acc0[OT], acc1[OT];
#pragma unroll
    for (int oo = 0; oo < OT; oo++) { acc0[oo] = NEG2; acc1[oo] = NEG2; }

    // ---- prologue: prefetch chunk 0 (x via cp.async, k via LDG+STS) ----
    stage_x(0, 0);
    cp_commit();
    {
        float a = gk[kof0];
        float c = gk[kof1];
        float e = (tid < KSLOT - 256) ? gk[kof2] : 0.f;
        k_sts(a, c, e, 0);
    }

    int bf = 0;
#pragma unroll 1
    for (int ch = 0; ch < NCH; ch++) {
        cp_wait<0>();         // x(ch) arrived (issued prev iter / prologue)
        __syncthreads();      // publish x(ch) + k(ch); slot bf^1 free
        float ka_f = 0.f, kc_f = 0.f, ke_f = 0.f;
        const bool have = (ch + 1 < NCH);
        if (have) {
            const int kc_ofs = (ch + 1) * CCH * 9;
            ka_f = gk[kof0 + kc_ofs];
            kc_f = gk[kof1 + kc_ofs];
            if (tid < KSLOT - 256) ke_f = gk[kof2 + kc_ofs];
            stage_x(ch + 1, bf ^ 1);
            cp_commit();
        }

        // ---- compute chunk ch: 24 (cl,ki) blocks, 1-block reg pipeline ----
        const __half*  xb  = sx + bf * BUFH;
        const __half2* skc = skr + bf * KSLOT;

        uint2    Eu; uint32_t Mu, Nu;
        uint4    ka, kb, kc;
        {   // prime block t=0 (cl=0, ki=0)
            const __half* row = xb + hl * HR;
            Eu = *(const uint2*)(row + wb + 8);
            Mu = *(const uint32_t*)(row + wb + 6);
            Nu = *(const uint32_t*)(row + wb + 12);
            const uint4* kq = (const uint4*)skc;
            ka = kq[0]; kb = kq[1]; kc = kq[2];
        }

#pragma unroll
        for (int t = 0; t < 3 * CCH; t++) {
            uint2 EuN; uint32_t MuN, NuN; uint4 kaN, kbN, kcN;
            if (t < 3 * CCH - 1) {
                const int tn  = t + 1;
                const int cln = tn / 3, kin = tn % 3;
                const __half* rowN = xb + (cln * XROWS + hl + kin) * HR;
                EuN = *(const uint2*)(rowN + wb + 8);
                MuN = *(const uint32_t*)(rowN + wb + 6);
                NuN = *(const uint32_t*)(rowN + wb + 12);
                const uint4* kqN = (const uint4*)(skc + (cln * 9 + kin * 3) * 4);
                kaN = kqN[0]; kbN = kqN[1]; kcN = kqN[2];
            }

            uint32_t O0u = __byte_perm(Mu,   Eu.x, 0x5432);  // (x[wb-1],x[wb])
            uint32_t O1u = __byte_perm(Eu.x, Eu.y, 0x5432);  // (x[wb+1],x[wb+2])
            uint32_t O2u = __byte_perm(Eu.y, Nu,   0x5432);  // (x[wb+3],x[wb+4])
            __half2 E0 = u2h(Eu.x), E1 = u2h(Eu.y);
            __half2 O0 = u2h(O0u), O1 = u2h(O1u), O2 = u2h(O2u);

            uint32_t k0a[4] = {ka.x, ka.y, ka.z, ka.w};
            uint32_t k1a[4] = {kb.x, kb.y, kb.z, kb.w};
            uint32_t k2a[4] = {kc.x, kc.y, kc.z, kc.w};

#pragma unroll
            for (int oo = 0; oo < OT; oo++) {
                __half2 k0 = u2h(k0a[oo]);
                __half2 k1 = u2h(k1a[oo]);
                __half2 k2 = u2h(k2a[oo]);
                __half2 a0 = acc0[oo], a1 = acc1[oo];
                a0 = __hmax2(a0, __hadd2(O0, k0));
                a1 = __hmax2(a1, __hadd2(O1, k0));
                a0 = __hmax2(a0, __hadd2(E0, k1));
                a1 = __hmax2(a1, __hadd2(E1, k1));
                a0 = __hmax2(a0, __hadd2(O1, k2));
                a1 = __hmax2(a1, __hadd2(O2, k2));
                acc0[oo] = a0; acc1[oo] = a1;
            }

            if (t < 3 * CCH - 1) {
                Eu = EuN; Mu = MuN; Nu = NuN;
                ka = kaN; kb = kbN; kc = kcN;
            }
        }

        // write next chunk's k into slot bf^1 (free: its old data was
        // consumed before this iteration's barrier)
        if (have)
            k_sts(ka_f, kc_f, ke_f, bf ^ 1);
        bf ^= 1;
    }

    // ---- write out: out[b][o_base+oo][h][wb..wb+3] ----
    const size_t obase = (((size_t)b * Oc + o_base) * Hc + h) * Wc + wb;
#pragma unroll
    for (int oo = 0; oo < OT; oo++) {
        float2 f0 = __half22float2(acc0[oo]);
        float2 f1 = __half22float2(acc1[oo]);
        *(float4*)(out + obase + (size_t)oo * Hc * Wc) =
            make_float4(f0.x, f0.y, f1.x, f1.y);
    }
}

extern "C" void kernel_launch(void* const* d_in, const int* in_sizes, int n_in,
                              void* d_out, int out_size)
{
    const float* x  = (const float*)d_in[0];   // [8,64,64,64]
    const float* k  = (const float*)d_in[1];   // [64,64,3,3]
    float* out      = (float*)d_out;           // [8,64,64,64]
    (void)in_sizes; (void)n_in; (void)out_size;

    // K1: x -> fp16 scratch (2M elems, 4 per thread, 256 thr/block)
    cvt_fp16_kernel<<<(Bc * Cc * Hc * Wc) / (4 * 256), 256>>>(x);
    // K2: main max-plus conv
    maxplus_fp16_kernel<<<1024, 128>>>(k, out);
}

// round 17
// speedup vs baseline: 1.6707x; 1.6707x over previous
#include <cuda_runtime.h>
#include <cuda_fp16.h>
#include <math_constants.h>
#include <cstdint>

// Max-plus conv2d in fp16x2, two-kernel version.
// K1: convert x fp32 -> fp16 scratch (4MB device global).
// K2: 128 thr = 16wq x 8hl; thread = 4o x 4w = 8 half2 accs; grid 1024.
//     CCH=8 -> 8 chunks, ONE barrier per chunk. x staged via cp.async
//     double-buffered ring (25.6 KB); k staged per-chunk via LDG fp32 ->
//     dup in regs -> STS ring (2.3 KB). Inner loop: nested, bounded unroll
//     (cl x2) -- NO flattened register pipeline (R16 showed it spills at 24
//     blocks / 64 regs).

constexpr int Cc  = 64;
constexpr int Hc  = 64;
constexpr int Wc  = 64;
constexpr int Oc  = 64;
constexpr int Bc  = 8;
constexpr int OT  = 4;
constexpr int HT  = 8;
constexpr int CCH = 8;
constexpr int NCH = Cc / CCH;            // 8 chunks
constexpr int XROWS = HT + 2;            // 10
constexpr int HR    = 80;                // halves per row (160B; col j = w + 8)
constexpr int BUFH  = CCH * XROWS * HR;  // 6400 halves per x ring slot
constexpr int NBUF  = 2;
constexpr int KSLOT = CCH * 9 * OT;      // 288 half2 per k ring slot

__device__ __align__(16) __half g_xh[Bc * Cc * Hc * Wc];   // 4 MB scratch

__global__ __launch_bounds__(256)
void cvt_fp16_kernel(const float* __restrict__ x)
{
    int i = (blockIdx.x * 256 + threadIdx.x) * 4;   // 2M elements total
    float4 v = *(const float4*)(x + i);
    __half2 a = __floats2half2_rn(v.x, v.y);
    __half2 b = __floats2half2_rn(v.z, v.w);
    uint2 u;
    u.x = *reinterpret_cast<uint32_t*>(&a);
    u.y = *reinterpret_cast<uint32_t*>(&b);
    *reinterpret_cast<uint2*>(g_xh + i) = u;
}

__device__ __forceinline__ void cp16(uint32_t s, const void* g) {
    asm volatile("cp.async.cg.shared.global [%0], [%1], 16;\n" :: "r"(s), "l"(g));
}
__device__ __forceinline__ void cp_commit() {
    asm volatile("cp.async.commit_group;\n" ::: "memory");
}
template <int N> __device__ __forceinline__ void cp_wait() {
    asm volatile("cp.async.wait_group %0;\n" :: "n"(N) : "memory");
}
__device__ __forceinline__ __half2 u2h(uint32_t u) {
    return *reinterpret_cast<__half2*>(&u);
}

__global__ __launch_bounds__(128, 7)
void maxplus_fp16_kernel(const float* __restrict__ gk,
                         float* __restrict__ out)
{
    __shared__ __align__(16) __half  sx[NBUF * BUFH];    // 25.6 KB
    __shared__ __align__(16) __half2 skr[NBUF * KSLOT];  // 2.3 KB

    const int bid = blockIdx.x;
    const int ht  = bid & 7;          // 8 h-tiles
    const int ot  = (bid >> 3) & 15;  // 16 o-tiles
    const int b   = bid >> 7;         // 8 batches

    const int h_base = ht * HT;
    const int o_base = ot * OT;

    const int tid = threadIdx.x;      // 0..127
    const int wq  = tid & 15;
    const int hl  = tid >> 4;         // 0..7
    const int wb  = wq * 4;
    const int h   = h_base + hl;

    const __half2 NEG2 = __half2half2(__float2half(-CUDART_INF_F));

    const uint32_t sx_u32 = (uint32_t)__cvta_generic_to_shared(sx);

    // ---- k staging indices: slot idx i -> (oo = i&3, r = i>>2 = cl*9+t) ----
    const int ki0 = tid;
    const int ki1 = tid + 128;
    const int ki2 = tid + 256;        // valid only tid < 32
    const int kof0 = (o_base + (ki0 & 3)) * (Cc * 9) + (ki0 >> 2);
    const int kof1 = (o_base + (ki1 & 3)) * (Cc * 9) + (ki1 >> 2);
    const int kof2 = (tid < KSLOT - 256) ? (o_base + (ki2 & 3)) * (Cc * 9) + (ki2 >> 2) : 0;

    auto k_sts = [&](float a, float c, float e, int bf) {
        __half2* dst = skr + bf * KSLOT;
        dst[ki0] = __half2half2(__float2half_rn(a));
        dst[ki1] = __half2half2(__float2half_rn(c));
        if (tid < KSLOT - 256)
            dst[ki2] = __half2half2(__float2half_rn(e));
    };

    // ---- prefill pads (cp.async never writes them), both x slots ----
    for (int rw = tid; rw < NBUF * CCH * XROWS; rw += 128) {
        *reinterpret_cast<__half2*>(sx + rw * HR + 6)  = NEG2;   // w=-2,-1
        *reinterpret_cast<__half2*>(sx + rw * HR + 72) = NEG2;   // w=64,65
    }
    // invalid h rows (ht==0 -> local row 0; ht==7 -> local row 9): interiors
    if (ht == 0 || ht == 7) {
        const int r = (ht == 0) ? 0 : (XROWS - 1);
        for (int i = tid; i < NBUF * CCH * 32; i += 128) {
            int j2 = i & 31;
            int cl = (i >> 5) & (CCH - 1);
            int bf = i / (CCH * 32);
            *reinterpret_cast<__half2*>(
                sx + bf * BUFH + (cl * XROWS + r) * HR + 8 + j2 * 2) = NEG2;
        }
    }

    // ---- x staging geometry: 640 cp16 per chunk = 5 per thread ----
    const __half* xsrc = g_xh + (size_t)b * Cc * Hc * Wc;
    int  gof[5], dof[5];
    bool vr[5];
#pragma unroll
    for (int jj = 0; jj < 5; jj++) {
        int idx = tid + 128 * jj;        // 0..639
        int q   = idx & 7;               // 8 cp16 per row (128B interior)
        int rw  = idx >> 3;              // cl*10 + r, 0..79
        int r   = rw % XROWS;
        int cl  = rw / XROWS;
        int hh  = h_base - 1 + r;
        vr[jj]  = (hh >= 0 && hh < Hc);
        gof[jj] = (cl * Hc + (vr[jj] ? hh : 0)) * Wc + q * 8;
        dof[jj] = (rw * HR + 8 + q * 8) * 2;   // bytes
    }

    auto stage_x = [&](int ch, int bf) {
        const __half* src = xsrc + (size_t)ch * CCH * Hc * Wc;
        const uint32_t dbase = sx_u32 + (uint32_t)(bf * BUFH * 2);
#pragma unroll
        for (int jj = 0; jj < 5; jj++)
            if (vr[jj])
                cp16(dbase + dof[jj], src + gof[jj]);
    };

    // accumulators: acc0[oo]=(wb,wb+1), acc1[oo]=(wb+2,wb+3)
    __half2 acc0[OT], acc1[OT];
#pragma unroll
    for (int oo = 0; oo < OT; oo++) { acc0[oo] = NEG2; acc1[oo] = NEG2; }

    // ---- prologue: chunk 0 (x via cp.async, k via LDG+STS) ----
    stage_x(0, 0);
    cp_commit();
    {
        float a = gk[kof0];
        float c = gk[kof1];
        float e = (tid < KSLOT - 256) ? gk[kof2] : 0.f;
        k_sts(a, c, e, 0);
    }

    int bf = 0;
#pragma unroll 1
    for (int ch = 0; ch < NCH; ch++) {
        cp_wait<0>();         // x(ch) arrived (issued prev iter / prologue)
        __syncthreads();      // publish x(ch)+k(ch); slot bf^1 free
        float ka_f = 0.f, kc_f = 0.f, ke_f = 0.f;
        const bool have = (ch + 1 < NCH);
        if (have) {
            const int kofs = (ch + 1) * CCH * 9;
            ka_f = gk[kof0 + kofs];
            kc_f = gk[kof1 + kofs];
            if (tid < KSLOT - 256) ke_f = gk[kof2 + kofs];
            stage_x(ch + 1, bf ^ 1);
            cp_commit();
        }

        // ---- compute chunk ch: nested loops, bounded unroll (no pipeline) ----
        const __half*  xb  = sx + bf * BUFH;
        const __half2* skc = skr + bf * KSLOT;

#pragma unroll 2
        for (int cl = 0; cl < CCH; cl++) {
#pragma unroll
            for (int ki = 0; ki < 3; ki++) {
                const __half* row = xb + (cl * XROWS + hl + ki) * HR;
                uint2    Eu = *(const uint2*)(row + wb + 8);
                uint32_t Mu = *(const uint32_t*)(row + wb + 6);
                uint32_t Nu = *(const uint32_t*)(row + wb + 12);
                uint32_t O0u = __byte_perm(Mu,   Eu.x, 0x5432);  // (x[wb-1],x[wb])
                uint32_t O1u = __byte_perm(Eu.x, Eu.y, 0x5432);  // (x[wb+1],x[wb+2])
                uint32_t O2u = __byte_perm(Eu.y, Nu,   0x5432);  // (x[wb+3],x[wb+4])
                __half2 E0 = u2h(Eu.x), E1 = u2h(Eu.y);
                __half2 O0 = u2h(O0u), O1 = u2h(O1u), O2 = u2h(O2u);

                const uint4* kp = (const uint4*)(skc + (cl * 9 + ki * 3) * 4);
                uint4 ka = kp[0];   // tap 0, oo 0..3
                uint4 kb = kp[1];   // tap 1
                uint4 kc = kp[2];   // tap 2
                uint32_t k0a[4] = {ka.x, ka.y, ka.z, ka.w};
                uint32_t k1a[4] = {kb.x, kb.y, kb.z, kb.w};
                uint32_t k2a[4] = {kc.x, kc.y, kc.z, kc.w};

#pragma unroll
                for (int oo = 0; oo < OT; oo++) {
                    __half2 k0 = u2h(k0a[oo]);
                    __half2 k1 = u2h(k1a[oo]);
                    __half2 k2 = u2h(k2a[oo]);
                    __half2 a0 = acc0[oo], a1 = acc1[oo];
                    a0 = __hmax2(a0, __hadd2(O0, k0));
                    a1 = __hmax2(a1, __hadd2(O1, k0));
                    a0 = __hmax2(a0, __hadd2(E0, k1));
                    a1 = __hmax2(a1, __hadd2(E1, k1));
                    a0 = __hmax2(a0, __hadd2(O1, k2));
                    a1 = __hmax2(a1, __hadd2(O2, k2));
                    acc0[oo] = a0; acc1[oo] = a1;
                }
            }
        }

        // write next chunk's k into slot bf^1 (old contents consumed before
        // this iteration's barrier)
        if (have)
            k_sts(ka_f, kc_f, ke_f, bf ^ 1);
        bf ^= 1;
    }

    // ---- write out: out[b][o_base+oo][h][wb..wb+3] ----
    const size_t obase = (((size_t)b * Oc + o_base) * Hc + h) * Wc + wb;
#pragma unroll
    for (int oo = 0; oo < OT; oo++) {
        float2 f0 = __half22float2(acc0[oo]);
        float2 f1 = __half22float2(acc1[oo]);
        *(float4*)(out + obase + (size_t)oo * Hc * Wc) =
            make_float4(f0.x, f0.y, f1.x, f1.y);
    }
}

extern "C" void kernel_launch(void* const* d_in, const int* in_sizes, int n_in,
                              void* d_out, int out_size)
{
    const float* x  = (const float*)d_in[0];   // [8,64,64,64]
    const float* k  = (const float*)d_in[1];   // [64,64,3,3]
    float* out      = (float*)d_out;           // [8,64,64,64]
    (void)in_sizes; (void)n_in; (void)out_size;

    // K1: x -> fp16 scratch
    cvt_fp16_kernel<<<(Bc * Cc * Hc * Wc) / (4 * 256), 256>>>(x);
    // K2: main max-plus conv
    maxplus_fp16_kernel<<<1024, 128>>>(k, out);
}